// round 1
// baseline (speedup 1.0000x reference)
#include <cuda_runtime.h>
#include <math.h>

#define D      512
#define NWAY   5
#define NKPTS  17
#define NS     25
#define BM     32
#define TPB    256

// scratch (allocation-free rule: __device__ globals)
__device__ float g_h1[NS * D];
__device__ float g_proto[NWAY * D];
__device__ float g_pn[NWAY];

// ---------------- prototype path ----------------

// h1 = relu(sf @ W1 + b1)   [25 x 512]
__global__ void proto_mlp1(const float* __restrict__ sf,
                           const float* __restrict__ W1,
                           const float* __restrict__ b1) {
    int s = blockIdx.x;      // 0..24
    int j = threadIdx.x;     // 0..511
    const float* srow = sf + s * D;
    float acc = b1[j];
    #pragma unroll 4
    for (int k = 0; k < D; k++)
        acc += srow[k] * W1[k * D + j];
    g_h1[s * D + j] = fmaxf(acc, 0.0f);
}

// proto_way[w] = mean_s(h1[w*5+s] @ W2) + b2 ; also pn[w] and prototypes output
__global__ void proto_mlp2(const float* __restrict__ W2,
                           const float* __restrict__ b2,
                           float* __restrict__ proto_out) {
    int w = blockIdx.x;      // 0..4
    int d = threadIdx.x;     // 0..511
    float acc = 0.0f;
    #pragma unroll 4
    for (int k = 0; k < D; k++) {
        float wv = W2[k * D + d];
        float hs = 0.0f;
        #pragma unroll
        for (int s = 0; s < 5; s++)
            hs += g_h1[(w * 5 + s) * D + k];
        acc += hs * wv;
    }
    float p = acc * 0.2f + b2[d];
    g_proto[w * D + d] = p;
    // prototypes output: broadcast over 17 keypoints
    for (int kp = 0; kp < NKPTS; kp++)
        proto_out[(size_t)(w * NKPTS + kp) * D + d] = p;
    // norm reduction
    __shared__ float red[D];
    red[d] = p * p;
    __syncthreads();
    for (int off = D / 2; off > 0; off >>= 1) {
        if (d < off) red[d] += red[d + off];
        __syncthreads();
    }
    if (d == 0) g_pn[w] = sqrtf(red[0]);
}

// ---------------- fused query kernel ----------------
// Per block: 32 queries. Phase1: norms + cosine distances + argmin.
// Phase2: hidden = relu(Q @ [Wo1|Wc1] + [bo1|bc1])  (32x512 GEMM tile)
// Phase3: offset/conf heads + all broadcast output writes.

__global__ void __launch_bounds__(TPB, 2)
query_kernel(const float* __restrict__ Q,  const float* __restrict__ IC,
             const float* __restrict__ Wo1, const float* __restrict__ bo1,
             const float* __restrict__ Wo2, const float* __restrict__ bo2,
             const float* __restrict__ Wc1, const float* __restrict__ bc1,
             const float* __restrict__ Wc2, const float* __restrict__ bc2,
             const float* __restrict__ temp,
             float* __restrict__ kp_out,  float* __restrict__ conf_out,
             float* __restrict__ dist_out, float* __restrict__ cls_out) {
    extern __shared__ float smem[];
    float* Qs     = smem;                 // BM*D floats (reused for hidden H)
    float* sproto = Qs + BM * D;          // NWAY*D
    float* sdist  = sproto + NWAY * D;    // BM*NWAY
    float* sclsf  = sdist + BM * NWAY;    // BM
    float* spn    = sclsf + BM;           // NWAY

    const int tid  = threadIdx.x;
    const int warp = tid >> 5;
    const int lane = tid & 31;
    const int q0   = blockIdx.x * BM;

    for (int i = tid; i < NWAY * D; i += TPB) sproto[i] = g_proto[i];
    if (tid < NWAY) spn[tid] = g_pn[tid];
    const float* Qg = Q + (size_t)q0 * D;
    for (int i = tid; i < BM * D; i += TPB) Qs[i] = Qg[i];
    __syncthreads();

    const float T = *temp;

    // ---- Phase 1: cosine distance + argmin (warp per 4 rows) ----
    for (int rr = 0; rr < BM / 8; rr++) {
        int r = warp * (BM / 8) + rr;
        float qq = 0.f, s0 = 0.f, s1 = 0.f, s2 = 0.f, s3 = 0.f, s4 = 0.f;
        for (int k = lane; k < D; k += 32) {
            float q = Qs[r * D + k];
            qq += q * q;
            s0 += q * sproto[0 * D + k];
            s1 += q * sproto[1 * D + k];
            s2 += q * sproto[2 * D + k];
            s3 += q * sproto[3 * D + k];
            s4 += q * sproto[4 * D + k];
        }
        #pragma unroll
        for (int off = 16; off > 0; off >>= 1) {
            qq += __shfl_xor_sync(0xffffffffu, qq, off);
            s0 += __shfl_xor_sync(0xffffffffu, s0, off);
            s1 += __shfl_xor_sync(0xffffffffu, s1, off);
            s2 += __shfl_xor_sync(0xffffffffu, s2, off);
            s3 += __shfl_xor_sync(0xffffffffu, s3, off);
            s4 += __shfl_xor_sync(0xffffffffu, s4, off);
        }
        if (lane == 0) {
            float qn = sqrtf(qq);
            float sv[5] = {s0, s1, s2, s3, s4};
            float best = 3.402823e38f;
            int bi = 0;
            #pragma unroll
            for (int w = 0; w < NWAY; w++) {
                float denom = fmaxf(qn * spn[w], 1e-8f);
                float dw = (1.0f - sv[w] / denom) / T;
                sdist[r * NWAY + w] = dw;
                if (dw < best) { best = dw; bi = w; }
            }
            sclsf[r] = (float)bi;
        }
    }

    // ---- Phase 2: 32x512x512 GEMM, 8x8 micro-tile per thread ----
    const int g  = tid >> 6;     // row group 0..3 (rows g*8 .. g*8+7)
    const int c  = tid & 63;     // col group (cols c*8 .. c*8+7)
    const int cb = c * 8;
    const float* Wb = (cb < 256) ? (Wo1 + cb) : (Wc1 + (cb - 256));
    const float* bb = (cb < 256) ? (bo1 + cb) : (bc1 + (cb - 256));
    const float* qbase = Qs + g * 8 * D;

    float acc[8][8];
    #pragma unroll
    for (int j = 0; j < 8; j++)
        #pragma unroll
        for (int i = 0; i < 8; i++) acc[j][i] = 0.f;

    for (int k = 0; k < D; k++) {
        float4 wa = *(const float4*)(Wb + (size_t)k * 256);
        float4 wc = *(const float4*)(Wb + (size_t)k * 256 + 4);
        float wv[8] = {wa.x, wa.y, wa.z, wa.w, wc.x, wc.y, wc.z, wc.w};
        float qv[8];
        #pragma unroll
        for (int j = 0; j < 8; j++) qv[j] = qbase[j * D + k];
        #pragma unroll
        for (int j = 0; j < 8; j++)
            #pragma unroll
            for (int i = 0; i < 8; i++)
                acc[j][i] += qv[j] * wv[i];
    }

    float bias[8];
    #pragma unroll
    for (int i = 0; i < 8; i++) bias[i] = bb[i];

    __syncthreads();   // everyone done reading Qs
    #pragma unroll
    for (int j = 0; j < 8; j++) {
        int r = g * 8 + j;
        float4 h0, h1v;
        h0.x = fmaxf(acc[j][0] + bias[0], 0.f);
        h0.y = fmaxf(acc[j][1] + bias[1], 0.f);
        h0.z = fmaxf(acc[j][2] + bias[2], 0.f);
        h0.w = fmaxf(acc[j][3] + bias[3], 0.f);
        h1v.x = fmaxf(acc[j][4] + bias[4], 0.f);
        h1v.y = fmaxf(acc[j][5] + bias[5], 0.f);
        h1v.z = fmaxf(acc[j][6] + bias[6], 0.f);
        h1v.w = fmaxf(acc[j][7] + bias[7], 0.f);
        *(float4*)(Qs + r * D + cb)     = h0;
        *(float4*)(Qs + r * D + cb + 4) = h1v;
    }
    __syncthreads();

    // ---- Phase 3: heads + output writes (warp per 4 rows) ----
    for (int rr = 0; rr < BM / 8; rr++) {
        int r = warp * (BM / 8) + rr;
        int q = q0 + r;
        float ox = 0.f, oy = 0.f, cl = 0.f;
        for (int i = lane; i < 256; i += 32) {
            float h  = Qs[r * D + i];
            ox += h * Wo2[i * 2 + 0];
            oy += h * Wo2[i * 2 + 1];
            float h2 = Qs[r * D + 256 + i];
            cl += h2 * Wc2[i];
        }
        #pragma unroll
        for (int off = 16; off > 0; off >>= 1) {
            ox += __shfl_xor_sync(0xffffffffu, ox, off);
            oy += __shfl_xor_sync(0xffffffffu, oy, off);
            cl += __shfl_xor_sync(0xffffffffu, cl, off);
        }
        float kx = 0.f, ky = 0.f, cf = 0.f;
        if (lane == 0) {
            ox += bo2[0]; oy += bo2[1]; cl += bc2[0];
            kx = (1.0f / (1.0f + expf(-ox))) * IC[(size_t)q * 2 + 0];
            ky = (1.0f / (1.0f + expf(-oy))) * IC[(size_t)q * 2 + 1];
            cf = 1.0f / (1.0f + expf(-cl));
        }
        kx = __shfl_sync(0xffffffffu, kx, 0);
        ky = __shfl_sync(0xffffffffu, ky, 0);
        cf = __shfl_sync(0xffffffffu, cf, 0);

        // keypoints [q][17][2]
        for (int l = lane; l < 2 * NKPTS; l += 32)
            kp_out[(size_t)q * (2 * NKPTS) + l] = (l & 1) ? ky : kx;
        // confidence [q][17]
        if (lane < NKPTS)
            conf_out[(size_t)q * NKPTS + lane] = cf;
        // distances [q][5][17]
        for (int l = lane; l < NWAY * NKPTS; l += 32)
            dist_out[(size_t)q * (NWAY * NKPTS) + l] = sdist[r * NWAY + l / NKPTS];
        // class prediction
        if (lane == 0)
            cls_out[q] = sclsf[r];
    }
}

extern "C" void kernel_launch(void* const* d_in, const int* in_sizes, int n_in,
                              void* d_out, int out_size) {
    const float* sf   = (const float*)d_in[0];
    // d_in[1] = support_keypoints (unused by reference math)
    const float* Q    = (const float*)d_in[2];
    const float* IC   = (const float*)d_in[3];
    const float* W1   = (const float*)d_in[4];
    const float* b1   = (const float*)d_in[5];
    const float* W2   = (const float*)d_in[6];
    const float* b2   = (const float*)d_in[7];
    const float* Wo1  = (const float*)d_in[8];
    const float* bo1  = (const float*)d_in[9];
    const float* Wo2  = (const float*)d_in[10];
    const float* bo2  = (const float*)d_in[11];
    const float* Wc1  = (const float*)d_in[12];
    const float* bc1  = (const float*)d_in[13];
    const float* Wc2  = (const float*)d_in[14];
    const float* bc2  = (const float*)d_in[15];
    const float* temp = (const float*)d_in[16];

    const int nq = in_sizes[2] / D;   // 65536

    float* out      = (float*)d_out;
    float* kp_out   = out;                                  // nq*34
    float* conf_out = kp_out   + (size_t)nq * 2 * NKPTS;    // nq*17
    float* dist_out = conf_out + (size_t)nq * NKPTS;        // nq*85
    float* cls_out  = dist_out + (size_t)nq * NWAY * NKPTS; // nq
    float* proto_out= cls_out  + (size_t)nq;                // 5*17*512

    proto_mlp1<<<NS, D>>>(sf, W1, b1);
    proto_mlp2<<<NWAY, D>>>(W2, b2, proto_out);

    size_t smem_bytes = (size_t)(BM * D + NWAY * D + BM * NWAY + BM + NWAY + 8) * sizeof(float);
    cudaFuncSetAttribute((const void*)query_kernel,
                         cudaFuncAttributeMaxDynamicSharedMemorySize, (int)smem_bytes);
    query_kernel<<<nq / BM, TPB, smem_bytes>>>(
        Q, IC, Wo1, bo1, Wo2, bo2, Wc1, bc1, Wc2, bc2, temp,
        kp_out, conf_out, dist_out, cls_out);
}

// round 2
// speedup vs baseline: 3.1127x; 3.1127x over previous
#include <cuda_runtime.h>
#include <math.h>
#include <stdint.h>

#define D      512
#define NWAY   5
#define NKPTS  17
#define BM     64
#define BN     256
#define KC     64
#define TPB    256
#define QS_STRIDE 72
#define WS_STRIDE 264
#define QS_BUF (BM*QS_STRIDE)     // 4608 floats
#define WS_BUF (KC*WS_STRIDE)     // 16896 floats

// scratch (__device__ globals: allocation-free rule)
__device__ float g_h1[25 * D];
__device__ float g_proto[NWAY * D];
__device__ float g_W[D * D];   // combined tf32-rounded weights [K][512]: cols 0..255 = Wo1, 256..511 = Wc1

// ---------------- helpers ----------------
__device__ __forceinline__ uint32_t f2tf32(float f) {
    uint32_t r; asm("cvt.rna.tf32.f32 %0, %1;" : "=r"(r) : "f"(f)); return r;
}
__device__ __forceinline__ void cpa16(void* dst, const void* src) {
    uint32_t d = (uint32_t)__cvta_generic_to_shared(dst);
    asm volatile("cp.async.cg.shared.global [%0], [%1], 16;" :: "r"(d), "l"(src));
}
__device__ __forceinline__ void cp_commit() { asm volatile("cp.async.commit_group;"); }
__device__ __forceinline__ void cp_wait1()  { asm volatile("cp.async.wait_group 1;"); }
__device__ __forceinline__ void cp_wait0()  { asm volatile("cp.async.wait_group 0;"); }

__device__ __forceinline__ void mma_tf32(float* d, const uint32_t* a, const uint32_t* b) {
    asm volatile("mma.sync.aligned.m16n8k8.row.col.f32.tf32.tf32.f32 "
        "{%0,%1,%2,%3},{%4,%5,%6,%7},{%8,%9},{%0,%1,%2,%3};"
        : "+f"(d[0]), "+f"(d[1]), "+f"(d[2]), "+f"(d[3])
        : "r"(a[0]), "r"(a[1]), "r"(a[2]), "r"(a[3]), "r"(b[0]), "r"(b[1]));
}

// ---------------- weight pre-convert + concat ----------------
__global__ void convW(const float* __restrict__ Wo1, const float* __restrict__ Wc1) {
    int k = blockIdx.x;
    int n = threadIdx.x;
    float v = (n < BN) ? Wo1[k * BN + n] : Wc1[k * BN + (n - BN)];
    uint32_t r = f2tf32(v);
    g_W[k * D + n] = __uint_as_float(r);
}

// ---------------- prototype path (k-parallel) ----------------
__global__ void proto1(const float* __restrict__ sf,
                       const float* __restrict__ W1,
                       const float* __restrict__ b1) {
    int s = blockIdx.x;
    int j = blockIdx.y * 64 + (threadIdx.x & 63);
    int kg = threadIdx.x >> 6;     // 0..3
    const float* srow = sf + s * D;
    float acc = 0.f;
    int k0 = kg * 128;
    #pragma unroll 8
    for (int k = k0; k < k0 + 128; k++)
        acc += srow[k] * W1[k * D + j];
    __shared__ float red[TPB];
    red[threadIdx.x] = acc;
    __syncthreads();
    if (threadIdx.x < 64) {
        float v = red[threadIdx.x] + red[threadIdx.x + 64] + red[threadIdx.x + 128]
                + red[threadIdx.x + 192] + b1[j];
        g_h1[s * D + j] = fmaxf(v, 0.f);
    }
}

__global__ void proto2(const float* __restrict__ W2,
                       const float* __restrict__ b2,
                       float* __restrict__ proto_out) {
    int w = blockIdx.x;
    __shared__ float hsum[D];
    int t = threadIdx.x;
    for (int k = t; k < D; k += TPB) {
        float a = 0.f;
        #pragma unroll
        for (int s = 0; s < 5; s++) a += g_h1[(w * 5 + s) * D + k];
        hsum[k] = a;
    }
    __syncthreads();
    int j = blockIdx.y * 64 + (t & 63);
    int kg = t >> 6;
    float acc = 0.f;
    int k0 = kg * 128;
    #pragma unroll 8
    for (int k = k0; k < k0 + 128; k++)
        acc += hsum[k] * W2[k * D + j];
    __shared__ float red[TPB];
    red[t] = acc;
    __syncthreads();
    if (t < 64) {
        float p = (red[t] + red[t + 64] + red[t + 128] + red[t + 192]) * 0.2f + b2[j];
        g_proto[w * D + j] = p;
        #pragma unroll
        for (int kp = 0; kp < NKPTS; kp++)
            proto_out[(size_t)(w * NKPTS + kp) * D + j] = p;
    }
}

// ---------------- fused query kernel ----------------
// gridDim = (nq/64, 2). y=0: offset head (+keypoints). y=1: conf head (+distances, cls).
__global__ void __launch_bounds__(TPB, 1)
query_kernel(const float* __restrict__ Q,   const float* __restrict__ IC,
             const float* __restrict__ bo1, const float* __restrict__ Wo2,
             const float* __restrict__ bo2,
             const float* __restrict__ bc1, const float* __restrict__ Wc2,
             const float* __restrict__ bc2,
             const float* __restrict__ temp,
             float* __restrict__ kp_out,  float* __restrict__ conf_out,
             float* __restrict__ dist_out, float* __restrict__ cls_out) {
    extern __shared__ float smem[];
    float* Qs      = smem;                      // 2 * 4608
    float* Ws      = Qs + 2 * QS_BUF;           // 2 * 16896
    float* sprotoT = Ws + 2 * WS_BUF;           // 512*8 (proto transposed [k][8], w<5 valid)
    float* sdist   = sprotoT + D * 8;           // 64*5
    float* scls    = sdist + BM * NWAY;         // 64
    float* spn     = scls + BM;                 // 8

    const int tid  = threadIdx.x;
    const int lane = tid & 31;
    const int warp = tid >> 5;
    const int q0   = blockIdx.x * BM;
    const int y    = blockIdx.y;
    const int n0   = y * BN;
    const int wm   = (warp & 1) * 32;           // warp row base
    const int wn   = (warp >> 1) * 64;          // warp col base
    const int g    = lane >> 2;
    const int qd   = lane & 3;

    // issue chunk 0 loads
    {
        #pragma unroll
        for (int i = 0; i < 4; i++) {
            int idx = tid + i * TPB; int row = idx >> 4, c4 = idx & 15;
            cpa16(Qs + row * QS_STRIDE + c4 * 4, Q + (size_t)(q0 + row) * D + c4 * 4);
        }
        #pragma unroll
        for (int i = 0; i < 16; i++) {
            int idx = tid + i * TPB; int row = idx >> 6, c4 = idx & 63;
            cpa16(Ws + row * WS_STRIDE + c4 * 4, g_W + (size_t)row * D + n0 + c4 * 4);
        }
        cp_commit();
    }

    if (y == 1) {
        for (int i = tid; i < D * 8; i += TPB) {
            int k = i >> 3, w = i & 7;
            sprotoT[i] = (w < NWAY) ? g_proto[w * D + k] : 0.f;
        }
    }

    float acc[2][8][4];
    #pragma unroll
    for (int mi = 0; mi < 2; mi++)
        #pragma unroll
        for (int ni = 0; ni < 8; ni++)
            #pragma unroll
            for (int i = 0; i < 4; i++) acc[mi][ni][i] = 0.f;

    float qq = 0.f, sw0 = 0.f, sw1 = 0.f, sw2 = 0.f, sw3 = 0.f, sw4 = 0.f;

    #pragma unroll 1
    for (int c = 0; c < 8; c++) {
        int buf = c & 1;
        if (c < 7) {
            int nb = buf ^ 1;
            float* qsd = Qs + nb * QS_BUF;
            float* wsd = Ws + nb * WS_BUF;
            int kc0 = (c + 1) * KC;
            #pragma unroll
            for (int i = 0; i < 4; i++) {
                int idx = tid + i * TPB; int row = idx >> 4, c4 = idx & 15;
                cpa16(qsd + row * QS_STRIDE + c4 * 4, Q + (size_t)(q0 + row) * D + kc0 + c4 * 4);
            }
            #pragma unroll
            for (int i = 0; i < 16; i++) {
                int idx = tid + i * TPB; int row = idx >> 6, c4 = idx & 63;
                cpa16(wsd + row * WS_STRIDE + c4 * 4, g_W + (size_t)(kc0 + row) * D + n0 + c4 * 4);
            }
            cp_commit();
            cp_wait1();
        } else {
            cp_wait0();
        }
        __syncthreads();

        const float* qs = Qs + buf * QS_BUF;
        const float* ws = Ws + buf * WS_BUF;

        // fused distance accumulation (exact fp32) — y==1 only
        if (y == 1) {
            int r = tid >> 2, q2 = tid & 3;
            const float* qp = qs + r * QS_STRIDE + q2 * 16;
            const float* pp = sprotoT + (c * KC + q2 * 16) * 8;
            #pragma unroll
            for (int i = 0; i < 16; i++) {
                float v = qp[i];
                qq += v * v;
                float4 pa = *(const float4*)(pp + i * 8);
                float  pb = pp[i * 8 + 4];
                sw0 += v * pa.x; sw1 += v * pa.y; sw2 += v * pa.z;
                sw3 += v * pa.w; sw4 += v * pb;
            }
        }

        // tf32 mma over this K-chunk
        #pragma unroll
        for (int ks = 0; ks < 8; ks++) {
            int k0 = ks * 8;
            uint32_t A[2][4];
            #pragma unroll
            for (int mi = 0; mi < 2; mi++) {
                const float* p = qs + (wm + mi * 16 + g) * QS_STRIDE + k0 + qd;
                A[mi][0] = f2tf32(p[0]);
                A[mi][2] = f2tf32(p[4]);
                A[mi][1] = f2tf32(p[8 * QS_STRIDE]);
                A[mi][3] = f2tf32(p[8 * QS_STRIDE + 4]);
            }
            uint32_t B[8][2];
            #pragma unroll
            for (int ni = 0; ni < 8; ni++) {
                const float* p = ws + (k0 + qd) * WS_STRIDE + wn + ni * 8 + g;
                B[ni][0] = __float_as_uint(p[0]);
                B[ni][1] = __float_as_uint(p[4 * WS_STRIDE]);
            }
            #pragma unroll
            for (int mi = 0; mi < 2; mi++)
                #pragma unroll
                for (int ni = 0; ni < 8; ni++)
                    mma_tf32(acc[mi][ni], A[mi], B[ni]);
        }
        __syncthreads();
    }

    // prototype norms (y==1)
    if (y == 1 && warp < NWAY) {
        float s = 0.f;
        for (int k = lane; k < D; k += 32) {
            float v = sprotoT[k * 8 + warp];
            s += v * v;
        }
        #pragma unroll
        for (int off = 16; off > 0; off >>= 1) s += __shfl_xor_sync(0xffffffffu, s, off);
        if (lane == 0) spn[warp] = sqrtf(s);
    }

    // store H = relu(acc + bias) into Ws buffer 0 (stride WS_STRIDE)
    {
        const float* bb = (y == 0) ? bo1 : bc1;
        float* Hs = Ws;
        #pragma unroll
        for (int ni = 0; ni < 8; ni++) {
            int colb = wn + ni * 8 + 2 * qd;
            float b0v = bb[colb], b1v = bb[colb + 1];
            #pragma unroll
            for (int mi = 0; mi < 2; mi++) {
                int r0 = wm + mi * 16 + g;
                Hs[r0 * WS_STRIDE + colb]           = fmaxf(acc[mi][ni][0] + b0v, 0.f);
                Hs[r0 * WS_STRIDE + colb + 1]       = fmaxf(acc[mi][ni][1] + b1v, 0.f);
                Hs[(r0 + 8) * WS_STRIDE + colb]     = fmaxf(acc[mi][ni][2] + b0v, 0.f);
                Hs[(r0 + 8) * WS_STRIDE + colb + 1] = fmaxf(acc[mi][ni][3] + b1v, 0.f);
            }
        }
    }
    __syncthreads();

    // finalize distances (y==1)
    if (y == 1) {
        #pragma unroll
        for (int off = 1; off <= 2; off <<= 1) {
            qq  += __shfl_xor_sync(0xffffffffu, qq,  off);
            sw0 += __shfl_xor_sync(0xffffffffu, sw0, off);
            sw1 += __shfl_xor_sync(0xffffffffu, sw1, off);
            sw2 += __shfl_xor_sync(0xffffffffu, sw2, off);
            sw3 += __shfl_xor_sync(0xffffffffu, sw3, off);
            sw4 += __shfl_xor_sync(0xffffffffu, sw4, off);
        }
        if ((tid & 3) == 0) {
            int r = tid >> 2;
            const float T = *temp;
            float qn = sqrtf(qq);
            float sv[5] = {sw0, sw1, sw2, sw3, sw4};
            float best = 3.402823e38f; int bi = 0;
            #pragma unroll
            for (int w = 0; w < NWAY; w++) {
                float denom = fmaxf(qn * spn[w], 1e-8f);
                float dv = (1.0f - sv[w] / denom) / T;
                sdist[r * NWAY + w] = dv;
                if (dv < best) { best = dv; bi = w; }
            }
            scls[r] = (float)bi;
        }
    }
    __syncthreads();

    // heads + output writes (warp handles 8 rows)
    const float* Hs = Ws;
    if (y == 0) {
        for (int rr = 0; rr < 8; rr++) {
            int r = warp * 8 + rr;
            int qi = q0 + r;
            float ox = 0.f, oy = 0.f;
            for (int i = lane; i < BN; i += 32) {
                float h = Hs[r * WS_STRIDE + i];
                ox += h * Wo2[2 * i];
                oy += h * Wo2[2 * i + 1];
            }
            #pragma unroll
            for (int off = 16; off > 0; off >>= 1) {
                ox += __shfl_xor_sync(0xffffffffu, ox, off);
                oy += __shfl_xor_sync(0xffffffffu, oy, off);
            }
            float kx = 0.f, ky = 0.f;
            if (lane == 0) {
                ox += bo2[0]; oy += bo2[1];
                kx = IC[(size_t)qi * 2 + 0] / (1.0f + expf(-ox));
                ky = IC[(size_t)qi * 2 + 1] / (1.0f + expf(-oy));
            }
            kx = __shfl_sync(0xffffffffu, kx, 0);
            ky = __shfl_sync(0xffffffffu, ky, 0);
            for (int l = lane; l < 2 * NKPTS; l += 32)
                kp_out[(size_t)qi * (2 * NKPTS) + l] = (l & 1) ? ky : kx;
        }
    } else {
        for (int rr = 0; rr < 8; rr++) {
            int r = warp * 8 + rr;
            int qi = q0 + r;
            float cl = 0.f;
            for (int i = lane; i < BN; i += 32)
                cl += Hs[r * WS_STRIDE + i] * Wc2[i];
            #pragma unroll
            for (int off = 16; off > 0; off >>= 1)
                cl += __shfl_xor_sync(0xffffffffu, cl, off);
            float cf = 0.f;
            if (lane == 0)
                cf = 1.0f / (1.0f + expf(-(cl + bc2[0])));
            cf = __shfl_sync(0xffffffffu, cf, 0);
            if (lane < NKPTS)
                conf_out[(size_t)qi * NKPTS + lane] = cf;
            for (int l = lane; l < NWAY * NKPTS; l += 32)
                dist_out[(size_t)qi * (NWAY * NKPTS) + l] = sdist[r * NWAY + l / NKPTS];
            if (lane == 0)
                cls_out[qi] = scls[r];
        }
    }
}

extern "C" void kernel_launch(void* const* d_in, const int* in_sizes, int n_in,
                              void* d_out, int out_size) {
    const float* sf   = (const float*)d_in[0];
    const float* Q    = (const float*)d_in[2];
    const float* IC   = (const float*)d_in[3];
    const float* W1   = (const float*)d_in[4];
    const float* b1   = (const float*)d_in[5];
    const float* W2   = (const float*)d_in[6];
    const float* b2   = (const float*)d_in[7];
    const float* Wo1  = (const float*)d_in[8];
    const float* bo1  = (const float*)d_in[9];
    const float* Wo2  = (const float*)d_in[10];
    const float* bo2  = (const float*)d_in[11];
    const float* Wc1  = (const float*)d_in[12];
    const float* bc1  = (const float*)d_in[13];
    const float* Wc2  = (const float*)d_in[14];
    const float* bc2  = (const float*)d_in[15];
    const float* temp = (const float*)d_in[16];

    const int nq = in_sizes[2] / D;   // 65536

    float* out       = (float*)d_out;
    float* kp_out    = out;
    float* conf_out  = kp_out   + (size_t)nq * 2 * NKPTS;
    float* dist_out  = conf_out + (size_t)nq * NKPTS;
    float* cls_out   = dist_out + (size_t)nq * NWAY * NKPTS;
    float* proto_out = cls_out  + (size_t)nq;

    convW<<<D, D>>>(Wo1, Wc1);
    proto1<<<dim3(25, 8), TPB>>>(sf, W1, b1);
    proto2<<<dim3(NWAY, 8), TPB>>>(W2, b2, proto_out);

    size_t smem_bytes = (size_t)(2 * QS_BUF + 2 * WS_BUF + D * 8 + BM * NWAY + BM + 8) * sizeof(float);
    cudaFuncSetAttribute((const void*)query_kernel,
                         cudaFuncAttributeMaxDynamicSharedMemorySize, (int)smem_bytes);
    query_kernel<<<dim3(nq / BM, 2), TPB, smem_bytes>>>(
        Q, IC, bo1, Wo2, bo2, bc1, Wc2, bc2, temp,
        kp_out, conf_out, dist_out, cls_out);
}